// round 1
// baseline (speedup 1.0000x reference)
#include <cuda_runtime.h>
#include <cuda_bf16.h>

// ExpanderLinear: out[b, o] = sum_k x[b,k] * W[o,k] * mask[o,k]
// x:      [8192, 4096] f32   (d_in[0])
// weight: [4096, 4096] f32   (d_in[1])
// mask:   [4096, 4096] f32   (d_in[2])
// out:    [8192, 4096] f32
//
// Round 0 baseline: classic SIMT fp32 tiled GEMM (C = A @ B^T), with the
// mask multiply fused into the B-tile shared-memory load. 128x128 C tile,
// BK=16, 256 threads, 8x8 accumulator per thread, float4 global loads.

#define BM 128
#define BN 128
#define BK 16
#define TM 8
#define TN 8
#define THREADS 256

static constexpr int M_DIM = 8192;  // batch
#define N_DIM 4096  // d_out
#define K_DIM 4096  // d_in

__global__ __launch_bounds__(THREADS)
void expander_gemm_f32(const float* __restrict__ X,
                       const float* __restrict__ W,
                       const float* __restrict__ Mk,
                       float* __restrict__ C) {
    // +1 padding on the BM/BN dim would change vectorized stores; keep simple,
    // accept minor bank conflicts for the baseline.
    __shared__ float As[BK][BM];
    __shared__ float Bs[BK][BN];

    const int tid = threadIdx.x;
    const int tx = tid % (BN / TN);   // 0..15  (column group)
    const int ty = tid / (BN / TN);   // 0..15  (row group)

    const int rowBase = blockIdx.y * BM;  // batch tile
    const int colBase = blockIdx.x * BN;  // d_out tile

    float acc[TM][TN];
    #pragma unroll
    for (int i = 0; i < TM; i++)
        #pragma unroll
        for (int j = 0; j < TN; j++)
            acc[i][j] = 0.0f;

    for (int kb = 0; kb < K_DIM; kb += BK) {
        // ---- load A tile (x): 128 rows x 16 k, as float4 along k ----
        // 128*16 = 2048 floats = 512 float4; 256 threads -> 2 each.
        #pragma unroll
        for (int i = 0; i < 2; i++) {
            int idx = tid + i * THREADS;      // 0..511
            int r   = idx >> 2;               // 0..127
            int k4  = (idx & 3) << 2;         // 0,4,8,12
            float4 v = *(const float4*)&X[(size_t)(rowBase + r) * K_DIM + kb + k4];
            As[k4 + 0][r] = v.x;
            As[k4 + 1][r] = v.y;
            As[k4 + 2][r] = v.z;
            As[k4 + 3][r] = v.w;
        }
        // ---- load B tile (W * mask): 128 rows (d_out) x 16 k ----
        #pragma unroll
        for (int i = 0; i < 2; i++) {
            int idx = tid + i * THREADS;
            int r   = idx >> 2;
            int k4  = (idx & 3) << 2;
            size_t g = (size_t)(colBase + r) * K_DIM + kb + k4;
            float4 w = *(const float4*)&W[g];
            float4 m = *(const float4*)&Mk[g];
            Bs[k4 + 0][r] = w.x * m.x;
            Bs[k4 + 1][r] = w.y * m.y;
            Bs[k4 + 2][r] = w.z * m.z;
            Bs[k4 + 3][r] = w.w * m.w;
        }
        __syncthreads();

        #pragma unroll
        for (int k = 0; k < BK; k++) {
            float a[TM], b[TN];
            #pragma unroll
            for (int i = 0; i < TM; i++) a[i] = As[k][ty * TM + i];
            #pragma unroll
            for (int j = 0; j < TN; j++) b[j] = Bs[k][tx * TN + j];
            #pragma unroll
            for (int i = 0; i < TM; i++)
                #pragma unroll
                for (int j = 0; j < TN; j++)
                    acc[i][j] = fmaf(a[i], b[j], acc[i][j]);
        }
        __syncthreads();
    }

    // ---- store C tile ----
    #pragma unroll
    for (int i = 0; i < TM; i++) {
        int r = rowBase + ty * TM + i;
        #pragma unroll
        for (int j = 0; j < TN; j += 4) {
            float4 v = make_float4(acc[i][j + 0], acc[i][j + 1],
                                   acc[i][j + 2], acc[i][j + 3]);
            *(float4*)&C[(size_t)r * N_DIM + colBase + tx * TN + j] = v;
        }
    }
}

extern "C" void kernel_launch(void* const* d_in, const int* in_sizes, int n_in,
                              void* d_out, int out_size) {
    const float* x    = (const float*)d_in[0];
    const float* w    = (const float*)d_in[1];
    const float* mask = (const float*)d_in[2];
    float* out        = (float*)d_out;

    dim3 grid(N_DIM / BN, M_DIM / BM);  // (32, 64)
    expander_gemm_f32<<<grid, THREADS>>>(x, w, mask, out);
}

// round 5
// speedup vs baseline: 3.6151x; 3.6151x over previous
#include <cuda_runtime.h>
#include <cuda_bf16.h>
#include <cstdint>

// ============================================================================
// ExpanderLinear: out = x @ (W*mask)^T    [8192,4096] @ [4096,4096]^T (f32)
//
// Harness ptxas target is plain sm_100 (no 'a' suffix) -> no tcgen05/TMEM.
// Use warp-level mma.sync (HMMA) bf16 with split precision:
//   x  = x_hi + x_lo (bf16),  wm = w*mask = wm_hi + wm_lo (bf16)
//   out ~= x_hi wm_hi^T + x_lo wm_hi^T + x_hi wm_lo^T     (drop lo*lo ~2^-18)
// One logical GEMM, K' = 12288, coordinate-folded over physical
//   Xc = [x_hi | x_lo]  (K=8192),  Wc = [wm_hi | wm_lo]  (K=8192).
// ============================================================================

#define M_DIM 8192
#define N_DIM 4096
#define K_DIM 4096
#define KK    8192
#define K_TOTAL 12288

#define BM 128
#define BN 128
#define BK 64
#define STAGES 3
#define ITERS (K_TOTAL / BK)          // 192

#define A_STAGE_BYTES (BM * BK * 2)   // 16384
#define B_STAGE_BYTES (BN * BK * 2)   // 16384
#define STAGE_BYTES   (A_STAGE_BYTES + B_STAGE_BYTES)   // 32768
#define SMEM_TOTAL    (STAGES * STAGE_BYTES)            // 98304

// ---- scratch (allocation-free) ----
__device__ __nv_bfloat16 g_Xc[(size_t)M_DIM * KK];   // 128 MB
__device__ __nv_bfloat16 g_Wc[(size_t)N_DIM * KK];   //  64 MB

// ---- PTX helpers ----
__device__ __forceinline__ uint32_t smem_u32(const void* p) {
    uint32_t a;
    asm("{ .reg .u64 t; cvta.to.shared.u64 t, %1; cvt.u32.u64 %0, t; }"
        : "=r"(a) : "l"(p));
    return a;
}

__device__ __forceinline__ void cp_async16(uint32_t dst, const void* src) {
    asm volatile("cp.async.cg.shared.global [%0], [%1], 16;\n"
                 :: "r"(dst), "l"(src));
}

__device__ __forceinline__ void cp_commit() {
    asm volatile("cp.async.commit_group;\n" ::: "memory");
}

template <int N>
__device__ __forceinline__ void cp_wait() {
    asm volatile("cp.async.wait_group %0;\n" :: "n"(N) : "memory");
}

__device__ __forceinline__ void ldmatrix_x4(uint32_t& r0, uint32_t& r1,
                                            uint32_t& r2, uint32_t& r3,
                                            uint32_t addr) {
    asm volatile("ldmatrix.sync.aligned.m8n8.x4.shared.b16 {%0,%1,%2,%3}, [%4];"
                 : "=r"(r0), "=r"(r1), "=r"(r2), "=r"(r3) : "r"(addr));
}

__device__ __forceinline__ void mma_16816(float* c, const uint32_t* a,
                                          const uint32_t* b) {
    asm volatile(
        "mma.sync.aligned.m16n8k16.row.col.f32.bf16.bf16.f32 "
        "{%0,%1,%2,%3}, {%4,%5,%6,%7}, {%8,%9}, {%0,%1,%2,%3};\n"
        : "+f"(c[0]), "+f"(c[1]), "+f"(c[2]), "+f"(c[3])
        : "r"(a[0]), "r"(a[1]), "r"(a[2]), "r"(a[3]), "r"(b[0]), "r"(b[1]));
}

// ============================================================================
// Conversion kernels: f32 -> (hi, lo) bf16 pairs with K-concatenated layout
// ============================================================================
__global__ void __launch_bounds__(256)
convert_x_kernel(const float* __restrict__ X, __nv_bfloat16* __restrict__ Xc) {
    size_t base = ((size_t)blockIdx.x * blockDim.x + threadIdx.x) * 4;
    size_t r = base >> 12;
    size_t c = base & 4095;
    float4 v = *(const float4*)(X + base);
    float xs[4] = {v.x, v.y, v.z, v.w};
    __nv_bfloat16 h[4], l[4];
#pragma unroll
    for (int i = 0; i < 4; i++) {
        h[i] = __float2bfloat16(xs[i]);
        l[i] = __float2bfloat16(xs[i] - __bfloat162float(h[i]));
    }
    __nv_bfloat162* dh = (__nv_bfloat162*)(Xc + r * KK + c);
    __nv_bfloat162* dl = (__nv_bfloat162*)(Xc + r * KK + 4096 + c);
    dh[0] = __halves2bfloat162(h[0], h[1]);
    dh[1] = __halves2bfloat162(h[2], h[3]);
    dl[0] = __halves2bfloat162(l[0], l[1]);
    dl[1] = __halves2bfloat162(l[2], l[3]);
}

__global__ void __launch_bounds__(256)
convert_w_kernel(const float* __restrict__ W, const float* __restrict__ Mk,
                 __nv_bfloat16* __restrict__ Wc) {
    size_t base = ((size_t)blockIdx.x * blockDim.x + threadIdx.x) * 4;
    size_t r = base >> 12;
    size_t c = base & 4095;
    float4 w = *(const float4*)(W + base);
    float4 m = *(const float4*)(Mk + base);
    float xs[4] = {w.x * m.x, w.y * m.y, w.z * m.z, w.w * m.w};
    __nv_bfloat16 h[4], l[4];
#pragma unroll
    for (int i = 0; i < 4; i++) {
        h[i] = __float2bfloat16(xs[i]);
        l[i] = __float2bfloat16(xs[i] - __bfloat162float(h[i]));
    }
    __nv_bfloat162* dh = (__nv_bfloat162*)(Wc + r * KK + c);
    __nv_bfloat162* dl = (__nv_bfloat162*)(Wc + r * KK + 4096 + c);
    dh[0] = __halves2bfloat162(h[0], h[1]);
    dh[1] = __halves2bfloat162(h[2], h[3]);
    dl[0] = __halves2bfloat162(l[0], l[1]);
    dl[1] = __halves2bfloat162(l[2], l[3]);
}

// ============================================================================
// GEMM kernel: 128x128 tile, BK=64, 3-stage cp.async, mma.sync bf16
// 256 threads = 8 warps as 2 (m) x 4 (n); warp tile 64x32.
// Smem: XOR-swizzled 16B chunks, conflict-free ldmatrix.
// ============================================================================
__device__ __forceinline__ void load_stage_A(uint32_t sA, const __nv_bfloat16* Ag,
                                             int tid) {
#pragma unroll
    for (int i = 0; i < 4; i++) {
        int c   = tid + i * 256;       // 0..1023
        int row = c >> 3;              // 0..127
        int cc  = c & 7;               // 16B chunk within 128B row
        uint32_t dst = sA + (uint32_t)(row * 8 + (cc ^ (row & 7))) * 16;
        cp_async16(dst, Ag + (size_t)row * KK + cc * 8);
    }
}

__device__ __forceinline__ void load_stage_B(uint32_t sB, const __nv_bfloat16* Bg,
                                             int tid) {
#pragma unroll
    for (int i = 0; i < 4; i++) {
        int c   = tid + i * 256;
        int row = c >> 3;
        int cc  = c & 7;
        uint32_t dst = sB + (uint32_t)(row * 8 + (cc ^ (row & 7))) * 16;
        cp_async16(dst, Bg + (size_t)row * KK + cc * 8);
    }
}

__global__ void __launch_bounds__(256, 2)
expander_mma_kernel(const __nv_bfloat16* __restrict__ Xc,
                    const __nv_bfloat16* __restrict__ Wc,
                    float* __restrict__ C) {
    extern __shared__ char smem[];
    const uint32_t sb = smem_u32(smem);

    const int tid  = threadIdx.x;
    const int wid  = tid >> 5;
    const int lid  = tid & 31;
    const int wm   = wid >> 2;        // 0..1  (m offset /64)
    const int wn   = wid & 3;         // 0..3  (n offset /32)
    const int mBase = blockIdx.x * BM;
    const int nBase = blockIdx.y * BN;

    // ldmatrix lane addressing constants
    const int grp   = lid >> 3;               // 0..3
    const int lane7 = lid & 7;
    const int a_row_off = ((grp & 1) << 3) + lane7;
    const int a_chk_off = grp >> 1;
    const int b_row_off = ((grp >> 1) << 3) + lane7;
    const int b_chk_off = grp & 1;

    float acc[4][4][4];               // [m16 tile][n8 tile][frag]
#pragma unroll
    for (int i = 0; i < 4; i++)
#pragma unroll
        for (int j = 0; j < 4; j++)
#pragma unroll
            for (int q = 0; q < 4; q++) acc[i][j][q] = 0.0f;

    const __nv_bfloat16* Abase = Xc + (size_t)mBase * KK;
    const __nv_bfloat16* Bbase = Wc + (size_t)nBase * KK;

    auto k_fold_a = [](int gk) { return (gk < KK) ? gk : gk - KK; };        // [hi|lo|hi]
    auto k_fold_b = [](int gk) { return (gk < K_DIM) ? gk : gk - K_DIM; };  // [hi|hi|lo]

    // ---- prologue: stages 0,1 ----
#pragma unroll
    for (int s = 0; s < STAGES - 1; s++) {
        const int gk = s * BK;
        load_stage_A(sb + s * STAGE_BYTES, Abase + k_fold_a(gk), tid);
        load_stage_B(sb + s * STAGE_BYTES + A_STAGE_BYTES, Bbase + k_fold_b(gk), tid);
        cp_commit();
    }

    int st = 0;
    for (int it = 0; it < ITERS; ++it) {
        cp_wait<STAGES - 2>();
        __syncthreads();   // stage st ready; also: all warps done reading the
                           // stage the upcoming prefetch will overwrite

        // prefetch stage it + STAGES-1
        if (it + STAGES - 1 < ITERS) {
            const int ps = (st + STAGES - 1 >= STAGES) ? st - 1 : st + STAGES - 1;
            const int gk = (it + STAGES - 1) * BK;
            load_stage_A(sb + ps * STAGE_BYTES, Abase + k_fold_a(gk), tid);
            load_stage_B(sb + ps * STAGE_BYTES + A_STAGE_BYTES, Bbase + k_fold_b(gk), tid);
        }
        cp_commit();   // commit every iter to keep wait_group bookkeeping uniform

        const uint32_t aS = sb + st * STAGE_BYTES;
        const uint32_t bS = aS + A_STAGE_BYTES;

#pragma unroll
        for (int k = 0; k < 4; k++) {          // 4 x k16 within BK=64
            uint32_t a[4][4], b[4][2];
#pragma unroll
            for (int mt = 0; mt < 4; mt++) {
                const int row = wm * 64 + mt * 16 + a_row_off;
                const uint32_t addr =
                    aS + (uint32_t)row * 128 + (uint32_t)(((k * 2 + a_chk_off) ^ lane7) * 16);
                ldmatrix_x4(a[mt][0], a[mt][1], a[mt][2], a[mt][3], addr);
            }
#pragma unroll
            for (int nt = 0; nt < 2; nt++) {
                const int row = wn * 32 + nt * 16 + b_row_off;
                const uint32_t addr =
                    bS + (uint32_t)row * 128 + (uint32_t)(((k * 2 + b_chk_off) ^ lane7) * 16);
                ldmatrix_x4(b[2 * nt][0], b[2 * nt][1], b[2 * nt + 1][0], b[2 * nt + 1][1], addr);
            }
#pragma unroll
            for (int mt = 0; mt < 4; mt++)
#pragma unroll
                for (int nt = 0; nt < 4; nt++)
                    mma_16816(acc[mt][nt], a[mt], b[nt]);
        }

        if (++st == STAGES) st = 0;
    }

    // ---- epilogue: direct f32 stores ----
    const int mRow = mBase + wm * 64;
    const int nCol = nBase + wn * 32;
#pragma unroll
    for (int mt = 0; mt < 4; mt++) {
#pragma unroll
        for (int nt = 0; nt < 4; nt++) {
            const int r0 = mRow + mt * 16 + (lid >> 2);
            const int c0 = nCol + nt * 8 + (lid & 3) * 2;
            float2 v0 = make_float2(acc[mt][nt][0], acc[mt][nt][1]);
            float2 v1 = make_float2(acc[mt][nt][2], acc[mt][nt][3]);
            *(float2*)(C + (size_t)r0 * N_DIM + c0) = v0;
            *(float2*)(C + (size_t)(r0 + 8) * N_DIM + c0) = v1;
        }
    }
}

// ============================================================================
// Host launch  (no static guards; cudaFuncSetAttribute is not a stream op,
// safe under graph capture and idempotent)
// ============================================================================
extern "C" void kernel_launch(void* const* d_in, const int* in_sizes, int n_in,
                              void* d_out, int out_size) {
    const float* x    = (const float*)d_in[0];
    const float* w    = (const float*)d_in[1];
    const float* mask = (const float*)d_in[2];
    float* out        = (float*)d_out;

    void* xc_ptr = nullptr;
    void* wc_ptr = nullptr;
    cudaGetSymbolAddress(&xc_ptr, g_Xc);
    cudaGetSymbolAddress(&wc_ptr, g_Wc);

    {
        size_t n4 = (size_t)M_DIM * K_DIM / 4;
        convert_x_kernel<<<(unsigned)(n4 / 256), 256>>>(x, (__nv_bfloat16*)xc_ptr);
    }
    {
        size_t n4 = (size_t)N_DIM * K_DIM / 4;
        convert_w_kernel<<<(unsigned)(n4 / 256), 256>>>(w, mask, (__nv_bfloat16*)wc_ptr);
    }

    cudaFuncSetAttribute(expander_mma_kernel,
                         cudaFuncAttributeMaxDynamicSharedMemorySize, SMEM_TOTAL);
    dim3 grid(M_DIM / BM, N_DIM / BN);   // (64, 32): m fastest -> B slab shared in L2
    expander_mma_kernel<<<grid, 256, SMEM_TOTAL>>>(
        (const __nv_bfloat16*)xc_ptr, (const __nv_bfloat16*)wc_ptr, out);
}